// round 14
// baseline (speedup 1.0000x reference)
#include <cuda_runtime.h>
#include <cuda_fp16.h>
#include <cstdint>

// Problem constants (dataset-fixed shapes).
static constexpr int NN    = 50000;      // nodes
static constexpr int HIDC  = 64;         // hidden/z dim
static constexpr int INDIM = 128;
static constexpr int N64   = NN * HIDC;  // 3,200,000
static constexpr int ECAP  = 1000000;    // edge capacity (dataset: 800000)
static constexpr int SCAN_BLK = 512;
static constexpr int SCAN_NB  = (NN + SCAN_BLK - 1) / SCAN_BLK;  // 98

// ---- scratch (device globals; no allocations allowed) ----
// g_cnt, g_sums, g_cntf are "self-cleaning": zero at module load, and each
// launch re-zeroes them (off the critical path) after their last reader.
__device__ int    g_cnt[NN];
__device__ int    g_offs[NN + 1];
__device__ int    g_cursor[NN];
__device__ int    g_bsum[SCAN_NB];
__device__ int2   g_edge[ECAP];       // (src, bitcast(norm)) bucketed by dst
__device__ float  g_dinv[NN];
__device__ __half g_XW[N64];          // x @ W1  (fp16 storage, fp32 math)
__device__ __half g_h1[N64];          // ELU(conv1)
__device__ float  g_sums[2 * 64 * 64];
__device__ float  g_cntf[64];

// ---------------- helpers ----------------
__device__ __forceinline__ void red_add_f32x4(float* p, float4 v) {
    asm volatile("red.global.add.v4.f32 [%0], {%1,%2,%3,%4};"
                 :: "l"(p), "f"(v.x), "f"(v.y), "f"(v.z), "f"(v.w) : "memory");
}
__device__ __forceinline__ void red_add_f32(float* p, float v) {
    asm volatile("red.global.add.f32 [%0], %1;" :: "l"(p), "f"(v) : "memory");
}
__device__ __forceinline__ float elu1(float x) { return x > 0.0f ? x : expm1f(x); }
__device__ __forceinline__ float4 elu4(float4 v) {
    v.x = elu1(v.x); v.y = elu1(v.y); v.z = elu1(v.z); v.w = elu1(v.w);
    return v;
}
__device__ __forceinline__ float4 fma4(float4 a, float s, float4 acc) {
    acc.x += a.x * s; acc.y += a.y * s; acc.z += a.z * s; acc.w += a.w * s;
    return acc;
}
__device__ __forceinline__ float4 add4(float4 a, float4 b) {
    a.x += b.x; a.y += b.y; a.z += b.z; a.w += b.w; return a;
}
// accumulate 8 halves (one uint4) scaled by w into acc[8]
__device__ __forceinline__ void fma8h(float* acc, uint4 raw, float w) {
    const __half2* h = reinterpret_cast<const __half2*>(&raw);
#pragma unroll
    for (int j = 0; j < 4; j++) {
        float2 f = __half22float2(h[j]);
        acc[2 * j]     += f.x * w;
        acc[2 * j + 1] += f.y * w;
    }
}
__device__ __forceinline__ uint4 pack8h(const float* a) {
    uint4 out;
    __half2* h = reinterpret_cast<__half2*>(&out);
#pragma unroll
    for (int j = 0; j < 4; j++) h[j] = __floats2half2_rn(a[2 * j], a[2 * j + 1]);
    return out;
}

// CSR gather (fp16 features, fp32 accum): 8 lanes/node, lane owns 8 halves (16B).
// Unrolled x8 (two interleaved 4-batches) for deeper MLP.
// NOTE: zeroes acc[] itself — returns ONLY the neighbor sum.
__device__ __forceinline__ void csr_gather_h(const __half* __restrict__ F,
                                             int node, int c, float* acc) {
    float acc2[8];
#pragma unroll
    for (int j = 0; j < 8; j++) { acc[j] = 0.f; acc2[j] = 0.f; }
    int beg = g_offs[node], end = g_offs[node + 1];
    int k = beg;
    for (; k + 8 <= end; k += 8) {
        int2 p0 = g_edge[k + 0];
        int2 p1 = g_edge[k + 1];
        int2 p2 = g_edge[k + 2];
        int2 p3 = g_edge[k + 3];
        int2 p4 = g_edge[k + 4];
        int2 p5 = g_edge[k + 5];
        int2 p6 = g_edge[k + 6];
        int2 p7 = g_edge[k + 7];
        uint4 v0 = *reinterpret_cast<const uint4*>(&F[(long long)p0.x * HIDC + c * 8]);
        uint4 v1 = *reinterpret_cast<const uint4*>(&F[(long long)p1.x * HIDC + c * 8]);
        uint4 v2 = *reinterpret_cast<const uint4*>(&F[(long long)p2.x * HIDC + c * 8]);
        uint4 v3 = *reinterpret_cast<const uint4*>(&F[(long long)p3.x * HIDC + c * 8]);
        uint4 v4 = *reinterpret_cast<const uint4*>(&F[(long long)p4.x * HIDC + c * 8]);
        uint4 v5 = *reinterpret_cast<const uint4*>(&F[(long long)p5.x * HIDC + c * 8]);
        uint4 v6 = *reinterpret_cast<const uint4*>(&F[(long long)p6.x * HIDC + c * 8]);
        uint4 v7 = *reinterpret_cast<const uint4*>(&F[(long long)p7.x * HIDC + c * 8]);
        fma8h(acc,  v0, __int_as_float(p0.y));
        fma8h(acc2, v1, __int_as_float(p1.y));
        fma8h(acc,  v2, __int_as_float(p2.y));
        fma8h(acc2, v3, __int_as_float(p3.y));
        fma8h(acc,  v4, __int_as_float(p4.y));
        fma8h(acc2, v5, __int_as_float(p5.y));
        fma8h(acc,  v6, __int_as_float(p6.y));
        fma8h(acc2, v7, __int_as_float(p7.y));
    }
    for (; k + 4 <= end; k += 4) {
        int2 p0 = g_edge[k + 0];
        int2 p1 = g_edge[k + 1];
        int2 p2 = g_edge[k + 2];
        int2 p3 = g_edge[k + 3];
        uint4 v0 = *reinterpret_cast<const uint4*>(&F[(long long)p0.x * HIDC + c * 8]);
        uint4 v1 = *reinterpret_cast<const uint4*>(&F[(long long)p1.x * HIDC + c * 8]);
        uint4 v2 = *reinterpret_cast<const uint4*>(&F[(long long)p2.x * HIDC + c * 8]);
        uint4 v3 = *reinterpret_cast<const uint4*>(&F[(long long)p3.x * HIDC + c * 8]);
        fma8h(acc,  v0, __int_as_float(p0.y));
        fma8h(acc2, v1, __int_as_float(p1.y));
        fma8h(acc,  v2, __int_as_float(p2.y));
        fma8h(acc2, v3, __int_as_float(p3.y));
    }
    for (; k < end; k++) {
        int2 p = g_edge[k];
        uint4 v = *reinterpret_cast<const uint4*>(&F[(long long)p.x * HIDC + c * 8]);
        fma8h(acc, v, __int_as_float(p.y));
    }
#pragma unroll
    for (int j = 0; j < 8; j++) acc[j] += acc2[j];
}

// ---------------- kernels ----------------

// Zero pooled sums/counts (side stream; only needed before gather2gemm2pool).
__global__ void k_zero_sums() {
    int i = blockIdx.x * blockDim.x + threadIdx.x;
    if (i < 2 * 64 * 64) g_sums[i] = 0.f;
    if (i < 64) g_cntf[i] = 0.f;
}

// Re-zero g_cnt AFTER scan1 has consumed it (side stream; next replay's k_deg
// then starts from zero — device globals are also zero at module load).
__global__ void k_zero_cnt() {
    int i = blockIdx.x * blockDim.x + threadIdx.x;
    if (i < NN / 4) reinterpret_cast<int4*>(g_cnt)[i] = make_int4(0, 0, 0, 0);
}

__global__ void k_deg(const int* __restrict__ dst, int E) {
    int e = blockIdx.x * blockDim.x + threadIdx.x;
    if (e < E) atomicAdd(&g_cnt[dst[e]], 1);
}

// block-local exclusive scan of counts (warp-shuffle); also dinv + per-block sums.
__global__ __launch_bounds__(SCAN_BLK) void k_scan1(int N) {
    __shared__ int wsum[16];
    const int tid  = threadIdx.x;
    const int lane = tid & 31;
    const int w    = tid >> 5;
    const int i    = blockIdx.x * SCAN_BLK + tid;

    int v = (i < N) ? g_cnt[i] : 0;
    if (i < N) g_dinv[i] = rsqrtf((float)v + 1.0f);  // +1 self loop

    int inc = v;
#pragma unroll
    for (int off = 1; off < 32; off <<= 1) {
        int t = __shfl_up_sync(0xFFFFFFFFu, inc, off);
        if (lane >= off) inc += t;
    }
    if (lane == 31) wsum[w] = inc;
    __syncthreads();
    if (w == 0) {
        int wv = (lane < 16) ? wsum[lane] : 0;
        int winc = wv;
#pragma unroll
        for (int off = 1; off < 16; off <<= 1) {
            int t = __shfl_up_sync(0xFFFFFFFFu, winc, off);
            if (lane >= off) winc += t;
        }
        if (lane < 16) wsum[lane] = winc - wv;     // exclusive warp base
        if (lane == 15) g_bsum[blockIdx.x] = winc; // block total
    }
    __syncthreads();

    if (i < N) g_offs[i] = wsum[w] + inc - v;
}

// Adds cross-block prefix (parallel Hillis-Steele over the 98 partials).
__global__ void k_scan3(int N, int E) {
    __shared__ int sb[128];
    int tid = threadIdx.x;
    if (tid < 128) sb[tid] = (tid < SCAN_NB) ? g_bsum[tid] : 0;
    __syncthreads();
#pragma unroll
    for (int off = 1; off < 128; off <<= 1) {
        int t = (tid < 128 && tid >= off) ? sb[tid - off] : 0;
        __syncthreads();
        if (tid < 128) sb[tid] += t;
        __syncthreads();
    }
    int i = blockIdx.x * blockDim.x + tid;
    if (i < N) {
        int blk = i / SCAN_BLK;
        int base = (blk == 0) ? 0 : sb[blk - 1];   // exclusive prefix
        int o = g_offs[i] + base;
        g_offs[i] = o;
        g_cursor[i] = o;
    }
    if (i == 0) g_offs[N] = E;
}

__global__ void k_fill(const int* __restrict__ src, const int* __restrict__ dst, int E) {
    int e = blockIdx.x * blockDim.x + threadIdx.x;
    if (e < E) {
        int d = dst[e];
        int s = src[e];
        int pos = atomicAdd(&g_cursor[d], 1);
        g_edge[pos] = make_int2(s, __float_as_int(g_dinv[s] * g_dinv[d]));
    }
}

// GEMM1: X[N,128] @ W[128,64] -> g_XW (fp16). 128 rows/block, 256 threads, 8 rows/thread.
__global__ __launch_bounds__(256) void k_gemm1(const float* __restrict__ X,
                                               const float* __restrict__ W, int N) {
    __shared__ float Ws[INDIM * HIDC];
    for (int i = threadIdx.x; i < INDIM * HIDC / 4; i += 256)
        reinterpret_cast<float4*>(Ws)[i] = reinterpret_cast<const float4*>(W)[i];
    __syncthreads();

    const int q  = threadIdx.x & 15;
    const int rg = threadIdx.x >> 4;       // 0..15
    const int row0 = blockIdx.x * 128;

    float4 acc[8];
    int rows[8]; bool valid[8];
#pragma unroll
    for (int rr = 0; rr < 8; rr++) {
        rows[rr] = row0 + rg + 16 * rr;
        valid[rr] = rows[rr] < N;
        acc[rr] = make_float4(0.f, 0.f, 0.f, 0.f);
    }

    for (int k4 = 0; k4 < INDIM / 4; k4++) {
        float4 a[8];
#pragma unroll
        for (int rr = 0; rr < 8; rr++)
            a[rr] = valid[rr]
                ? reinterpret_cast<const float4*>(&X[(long long)rows[rr] * INDIM + k4 * 4])[0]
                : make_float4(0.f, 0.f, 0.f, 0.f);
#pragma unroll
        for (int kk = 0; kk < 4; kk++) {
            float4 w = reinterpret_cast<const float4*>(&Ws[(k4 * 4 + kk) * HIDC + q * 4])[0];
#pragma unroll
            for (int rr = 0; rr < 8; rr++) {
                float av = (&a[rr].x)[kk];
                acc[rr] = fma4(w, av, acc[rr]);
            }
        }
    }
#pragma unroll
    for (int rr = 0; rr < 8; rr++) {
        if (valid[rr]) {
            uint2 p;
            reinterpret_cast<__half2*>(&p)[0] = __floats2half2_rn(acc[rr].x, acc[rr].y);
            reinterpret_cast<__half2*>(&p)[1] = __floats2half2_rn(acc[rr].z, acc[rr].w);
            *reinterpret_cast<uint2*>(&g_XW[(long long)rows[rr] * HIDC + q * 4]) = p;
        }
    }
}

// Layer-1 CSR gather + self-loop + bias + ELU -> g_h1. 8 lanes/node, 8 floats/lane.
__global__ void k_gather1(const float* __restrict__ b1, int N) {
    long long idx = (long long)blockIdx.x * blockDim.x + threadIdx.x;
    if (idx >= (long long)N * 8) return;
    int node = (int)(idx >> 3);
    int c    = (int)(idx & 7);
    float di = g_dinv[node];
    float self = di * di;

    float acc[8];
    csr_gather_h(g_XW, node, c, acc);   // neighbor sum (zeroes acc itself)
    {
        uint4 v = *reinterpret_cast<const uint4*>(&g_XW[(long long)node * HIDC + c * 8]);
        const __half2* h = reinterpret_cast<const __half2*>(&v);
#pragma unroll
        for (int j = 0; j < 4; j++) {
            float2 f = __half22float2(h[j]);
            acc[2 * j]     += f.x * self;
            acc[2 * j + 1] += f.y * self;
        }
    }

#pragma unroll
    for (int j = 0; j < 8; j++) {
        acc[j] += b1[c * 8 + j];
        acc[j] = elu1(acc[j]);
    }
    *reinterpret_cast<uint4*>(&g_h1[(long long)node * HIDC + c * 8]) = pack8h(acc);
}

// Fused layer-2: CSR gather h1 into smem tile (64 nodes), then
// z = tile @ {Wmu,Wsig} + bias, ELU, mean-pool accumulate. 256 threads/block.
__global__ __launch_bounds__(256) void k_gather2gemm2pool(
        const float* __restrict__ Wmu, const float* __restrict__ bmu,
        const float* __restrict__ Wsig, const float* __restrict__ bsig,
        const int* __restrict__ batch, int N) {
    __shared__ float Wms[HIDC * HIDC];
    __shared__ float Wss[HIDC * HIDC];
    __shared__ float tile[64 * HIDC];   // 16 KB
    __shared__ float spool[128];        // 64 mu + 64 sig

    for (int i = threadIdx.x; i < HIDC * HIDC / 4; i += 256) {
        reinterpret_cast<float4*>(Wms)[i] = reinterpret_cast<const float4*>(Wmu)[i];
        reinterpret_cast<float4*>(Wss)[i] = reinterpret_cast<const float4*>(Wsig)[i];
    }
    if (threadIdx.x < 128) spool[threadIdx.x] = 0.f;

    const int row0 = blockIdx.x * 64;

    // ---- Phase A: gather 64 nodes into smem tile (8 lanes/node, 2 nodes/thread) ----
    {
        int c  = threadIdx.x & 7;      // 8-half slice
        int ng = threadIdx.x >> 3;     // 0..31
#pragma unroll
        for (int pp = 0; pp < 2; pp++) {
            int ln = ng + 32 * pp;     // local node 0..63
            int node = row0 + ln;
            float acc[8];
            if (node < N) {
                float di = g_dinv[node];
                float self = di * di;
                csr_gather_h(g_h1, node, c, acc);   // zeroes acc itself
                uint4 v = *reinterpret_cast<const uint4*>(&g_h1[(long long)node * HIDC + c * 8]);
                const __half2* h = reinterpret_cast<const __half2*>(&v);
#pragma unroll
                for (int j = 0; j < 4; j++) {
                    float2 f = __half22float2(h[j]);
                    acc[2 * j]     += f.x * self;
                    acc[2 * j + 1] += f.y * self;
                }
            } else {
#pragma unroll
                for (int j = 0; j < 8; j++) acc[j] = 0.f;
            }
            reinterpret_cast<float4*>(&tile[ln * HIDC + c * 8])[0] =
                make_float4(acc[0], acc[1], acc[2], acc[3]);
            reinterpret_cast<float4*>(&tile[ln * HIDC + c * 8 + 4])[0] =
                make_float4(acc[4], acc[5], acc[6], acc[7]);
        }
    }
    __syncthreads();

    // ---- Phase B: dual GEMM from smem + bias + ELU + pool ----
    const int q  = threadIdx.x & 15;
    const int rg = threadIdx.x >> 4;   // 0..15

    float4 am[4], as4[4];
    int rows[4]; bool valid[4];
#pragma unroll
    for (int rr = 0; rr < 4; rr++) {
        rows[rr] = row0 + rg + 16 * rr;
        valid[rr] = rows[rr] < N;
        am[rr]  = make_float4(0.f, 0.f, 0.f, 0.f);
        as4[rr] = make_float4(0.f, 0.f, 0.f, 0.f);
    }

    for (int k4 = 0; k4 < HIDC / 4; k4++) {
        float4 a[4];
#pragma unroll
        for (int rr = 0; rr < 4; rr++)
            a[rr] = reinterpret_cast<const float4*>(&tile[(rg + 16 * rr) * HIDC + k4 * 4])[0];
#pragma unroll
        for (int kk = 0; kk < 4; kk++) {
            float4 wm = reinterpret_cast<const float4*>(&Wms[(k4 * 4 + kk) * HIDC + q * 4])[0];
            float4 ws = reinterpret_cast<const float4*>(&Wss[(k4 * 4 + kk) * HIDC + q * 4])[0];
#pragma unroll
            for (int rr = 0; rr < 4; rr++) {
                float av = (&a[rr].x)[kk];
                am[rr]  = fma4(wm, av, am[rr]);
                as4[rr] = fma4(ws, av, as4[rr]);
            }
        }
    }

    float4 bbm = reinterpret_cast<const float4*>(&bmu[q * 4])[0];
    float4 bbs = reinterpret_cast<const float4*>(&bsig[q * 4])[0];
#pragma unroll
    for (int rr = 0; rr < 4; rr++) {
        am[rr]  = elu4(add4(am[rr], bbm));
        as4[rr] = elu4(add4(as4[rr], bbs));
    }

    int lastRow = min(row0 + 63, N - 1);
    int g0 = batch[row0];
    int g1 = batch[lastRow];

    if (g0 == g1) {
        float4 sm = make_float4(0.f, 0.f, 0.f, 0.f);
        float4 ss = make_float4(0.f, 0.f, 0.f, 0.f);
#pragma unroll
        for (int rr = 0; rr < 4; rr++) {
            if (valid[rr]) { sm = add4(sm, am[rr]); ss = add4(ss, as4[rr]); }
        }
        atomicAdd(&spool[q * 4 + 0], sm.x);
        atomicAdd(&spool[q * 4 + 1], sm.y);
        atomicAdd(&spool[q * 4 + 2], sm.z);
        atomicAdd(&spool[q * 4 + 3], sm.w);
        atomicAdd(&spool[64 + q * 4 + 0], ss.x);
        atomicAdd(&spool[64 + q * 4 + 1], ss.y);
        atomicAdd(&spool[64 + q * 4 + 2], ss.z);
        atomicAdd(&spool[64 + q * 4 + 3], ss.w);
        __syncthreads();
        if (threadIdx.x < 32) {
            int half = threadIdx.x >> 4;
            int cc   = threadIdx.x & 15;
            float4 v = reinterpret_cast<const float4*>(&spool[half * 64 + cc * 4])[0];
            red_add_f32x4(&g_sums[(long long)(half * 64 + g0) * HIDC + cc * 4], v);
        }
        if (threadIdx.x == 0) {
            int cnt = min(N - row0, 64);
            red_add_f32(&g_cntf[g0], (float)cnt);
        }
    } else {
#pragma unroll
        for (int rr = 0; rr < 4; rr++) {
            if (!valid[rr]) continue;
            int g = batch[rows[rr]];
            red_add_f32x4(&g_sums[(long long)(0 * 64 + g) * HIDC + q * 4], am[rr]);
            red_add_f32x4(&g_sums[(long long)(1 * 64 + g) * HIDC + q * 4], as4[rr]);
            if (q == 0) red_add_f32(&g_cntf[g], 1.0f);
        }
    }
}

// Final: divide by counts, write [z_mu ; z_sigma] to d_out.
__global__ void k_final(float* __restrict__ out, int G) {
    int tid = blockIdx.x * blockDim.x + threadIdx.x;
    int total = 2 * G * HIDC;
    if (tid >= total) return;
    int t = tid / (G * HIDC);
    int rem = tid - t * G * HIDC;
    int g = rem >> 6;
    int c = rem & 63;
    float cnt = fmaxf(g_cntf[g], 1.0f);
    out[tid] = g_sums[(long long)(t * 64 + g) * HIDC + c] / cnt;
}

// ---------------- launch ----------------
extern "C" void kernel_launch(void* const* d_in, const int* in_sizes, int n_in,
                              void* d_out, int out_size) {
    const float* x     = (const float*)d_in[0];
    const int*   ei    = (const int*)d_in[1];
    const int*   batch = (const int*)d_in[2];

    int N = in_sizes[0] / INDIM;   // 50000
    int E = in_sizes[1] / 2;       // 800000
    int G = out_size / (2 * HIDC); // 64

    int wi = 3;
    if (in_sizes[3] == 1) wi = 4;  // num_graphs may be materialized
    const float* W1   = (const float*)d_in[wi + 0];
    const float* b1   = (const float*)d_in[wi + 1];
    const float* Wmu  = (const float*)d_in[wi + 2];
    const float* bmu  = (const float*)d_in[wi + 3];
    const float* Wsig = (const float*)d_in[wi + 4];
    const float* bsig = (const float*)d_in[wi + 5];
    float* out = (float*)d_out;

    const int* src = ei;
    const int* dst = ei + E;

    // Fork-join: CSR build chain on the main (capture) stream; gemm1 + sums
    // zeroing + cnt re-zero on a side stream. ALL side-stream work is joined
    // back into stream 0 before capture ends (evJ before gather1, evZ before
    // k_final) so the graph has a single sink.
    cudaStream_t s2;
    cudaStreamCreateWithFlags(&s2, cudaStreamNonBlocking);
    cudaEvent_t evF, evJ, evS, evZ;
    cudaEventCreateWithFlags(&evF, cudaEventDisableTiming);
    cudaEventCreateWithFlags(&evJ, cudaEventDisableTiming);
    cudaEventCreateWithFlags(&evS, cudaEventDisableTiming);
    cudaEventCreateWithFlags(&evZ, cudaEventDisableTiming);

    cudaEventRecord(evF, 0);
    cudaStreamWaitEvent(s2, evF, 0);
    k_zero_sums<<<(2 * 64 * 64 + 255) / 256, 256, 0, s2>>>();   // branch B
    k_gemm1<<<(N + 127) / 128, 256, 0, s2>>>(x, W1, N);
    cudaEventRecord(evJ, s2);

    // branch A: CSR build (g_cnt arrives zeroed: module-load zero-init on the
    // first call; re-zeroed below on every call after scan1 consumes it).
    k_deg<<<(E + 255) / 256, 256>>>(dst, E);
    k_scan1<<<SCAN_NB, SCAN_BLK>>>(N);
    cudaEventRecord(evS, 0);
    k_scan3<<<(N + 255) / 256, 256>>>(N, E);
    k_fill<<<(E + 255) / 256, 256>>>(src, dst, E);

    // side stream: re-zero g_cnt once scan1 has read it (hidden under k_fill).
    cudaStreamWaitEvent(s2, evS, 0);
    k_zero_cnt<<<(NN / 4 + 255) / 256, 256, 0, s2>>>();
    cudaEventRecord(evZ, s2);

    cudaStreamWaitEvent(0, evJ, 0);   // join (gemm1 + zero_sums) before gather1

    {
        long long t = (long long)N * 8;
        k_gather1<<<(unsigned)((t + 255) / 256), 256>>>(b1, N);
    }
    k_gather2gemm2pool<<<(N + 63) / 64, 256>>>(Wmu, bmu, Wsig, bsig, batch, N);

    cudaStreamWaitEvent(0, evZ, 0);   // fold cnt re-zero into the main chain
    k_final<<<(2 * G * HIDC + 255) / 256, 256>>>(out, G);

    cudaEventDestroy(evF);
    cudaEventDestroy(evJ);
    cudaEventDestroy(evS);
    cudaEventDestroy(evZ);
    cudaStreamDestroy(s2);
}

// round 15
// speedup vs baseline: 1.1199x; 1.1199x over previous
#include <cuda_runtime.h>
#include <cuda_fp16.h>
#include <cstdint>

// Problem constants (dataset-fixed shapes).
static constexpr int NN    = 50000;      // nodes
static constexpr int HIDC  = 64;         // hidden/z dim
static constexpr int INDIM = 128;
static constexpr int N64   = NN * HIDC;  // 3,200,000
static constexpr int ECAP  = 1000000;    // edge capacity (dataset: 800000)
static constexpr int SCAN_BLK = 512;
static constexpr int SCAN_NB  = (NN + SCAN_BLK - 1) / SCAN_BLK;  // 98

// ---- scratch (device globals; no allocations allowed) ----
// g_cnt, g_sums, g_cntf are "self-cleaning": zero at module load, and each
// launch re-zeroes them (off the critical path) after their last reader.
__device__ int    g_cnt[NN];
__device__ int    g_offs[NN + 1];
__device__ int    g_cursor[NN];
__device__ int    g_bsum[SCAN_NB];
__device__ int2   g_edge[ECAP];       // (src, bitcast(norm)) bucketed by dst
__device__ float  g_dinv[NN];
__device__ __half g_XW[N64];          // x @ W1  (fp16 storage, fp32 math)
__device__ __half g_h1[N64];          // ELU(conv1)
__device__ float  g_sums[2 * 64 * 64];
__device__ float  g_cntf[64];

// ---------------- helpers ----------------
__device__ __forceinline__ void red_add_f32x4(float* p, float4 v) {
    asm volatile("red.global.add.v4.f32 [%0], {%1,%2,%3,%4};"
                 :: "l"(p), "f"(v.x), "f"(v.y), "f"(v.z), "f"(v.w) : "memory");
}
__device__ __forceinline__ void red_add_f32(float* p, float v) {
    asm volatile("red.global.add.f32 [%0], %1;" :: "l"(p), "f"(v) : "memory");
}
__device__ __forceinline__ float elu1(float x) { return x > 0.0f ? x : expm1f(x); }
__device__ __forceinline__ float4 elu4(float4 v) {
    v.x = elu1(v.x); v.y = elu1(v.y); v.z = elu1(v.z); v.w = elu1(v.w);
    return v;
}
__device__ __forceinline__ float4 fma4(float4 a, float s, float4 acc) {
    acc.x += a.x * s; acc.y += a.y * s; acc.z += a.z * s; acc.w += a.w * s;
    return acc;
}
__device__ __forceinline__ float4 add4(float4 a, float4 b) {
    a.x += b.x; a.y += b.y; a.z += b.z; a.w += b.w; return a;
}
// accumulate 8 halves (one uint4) scaled by w into acc[8]
__device__ __forceinline__ void fma8h(float* acc, uint4 raw, float w) {
    const __half2* h = reinterpret_cast<const __half2*>(&raw);
#pragma unroll
    for (int j = 0; j < 4; j++) {
        float2 f = __half22float2(h[j]);
        acc[2 * j]     += f.x * w;
        acc[2 * j + 1] += f.y * w;
    }
}
__device__ __forceinline__ uint4 pack8h(const float* a) {
    uint4 out;
    __half2* h = reinterpret_cast<__half2*>(&out);
#pragma unroll
    for (int j = 0; j < 4; j++) h[j] = __floats2half2_rn(a[2 * j], a[2 * j + 1]);
    return out;
}

// CSR gather (fp16 features, fp32 accum): 8 lanes/node, lane owns 8 halves (16B).
// Unrolled x4 (verified-fast R11 version). ACCUMULATES into caller-seeded acc[8].
__device__ __forceinline__ void csr_gather_h(const __half* __restrict__ F,
                                             int node, int c, float* acc) {
    float acc2[8];
#pragma unroll
    for (int j = 0; j < 8; j++) acc2[j] = 0.f;
    int beg = g_offs[node], end = g_offs[node + 1];
    int k = beg;
    for (; k + 4 <= end; k += 4) {
        int2 p0 = g_edge[k + 0];
        int2 p1 = g_edge[k + 1];
        int2 p2 = g_edge[k + 2];
        int2 p3 = g_edge[k + 3];
        uint4 v0 = *reinterpret_cast<const uint4*>(&F[(long long)p0.x * HIDC + c * 8]);
        uint4 v1 = *reinterpret_cast<const uint4*>(&F[(long long)p1.x * HIDC + c * 8]);
        uint4 v2 = *reinterpret_cast<const uint4*>(&F[(long long)p2.x * HIDC + c * 8]);
        uint4 v3 = *reinterpret_cast<const uint4*>(&F[(long long)p3.x * HIDC + c * 8]);
        fma8h(acc,  v0, __int_as_float(p0.y));
        fma8h(acc2, v1, __int_as_float(p1.y));
        fma8h(acc,  v2, __int_as_float(p2.y));
        fma8h(acc2, v3, __int_as_float(p3.y));
    }
    for (; k < end; k++) {
        int2 p = g_edge[k];
        uint4 v = *reinterpret_cast<const uint4*>(&F[(long long)p.x * HIDC + c * 8]);
        fma8h(acc, v, __int_as_float(p.y));
    }
#pragma unroll
    for (int j = 0; j < 8; j++) acc[j] += acc2[j];
}

// ---------------- kernels ----------------

// Zero pooled sums/counts (side stream; only needed before gather2gemm2pool).
__global__ void k_zero_sums() {
    int i = blockIdx.x * blockDim.x + threadIdx.x;
    if (i < 2 * 64 * 64) g_sums[i] = 0.f;
    if (i < 64) g_cntf[i] = 0.f;
}

// Re-zero g_cnt AFTER scan1 has consumed it (side stream; next replay's k_deg
// then starts from zero — device globals are also zero at module load).
__global__ void k_zero_cnt() {
    int i = blockIdx.x * blockDim.x + threadIdx.x;
    if (i < NN / 4) reinterpret_cast<int4*>(g_cnt)[i] = make_int4(0, 0, 0, 0);
}

__global__ void k_deg(const int* __restrict__ dst, int E) {
    int e = blockIdx.x * blockDim.x + threadIdx.x;
    if (e < E) atomicAdd(&g_cnt[dst[e]], 1);
}

// block-local exclusive scan of counts (warp-shuffle); also dinv + per-block sums.
__global__ __launch_bounds__(SCAN_BLK) void k_scan1(int N) {
    __shared__ int wsum[16];
    const int tid  = threadIdx.x;
    const int lane = tid & 31;
    const int w    = tid >> 5;
    const int i    = blockIdx.x * SCAN_BLK + tid;

    int v = (i < N) ? g_cnt[i] : 0;
    if (i < N) g_dinv[i] = rsqrtf((float)v + 1.0f);  // +1 self loop

    int inc = v;
#pragma unroll
    for (int off = 1; off < 32; off <<= 1) {
        int t = __shfl_up_sync(0xFFFFFFFFu, inc, off);
        if (lane >= off) inc += t;
    }
    if (lane == 31) wsum[w] = inc;
    __syncthreads();
    if (w == 0) {
        int wv = (lane < 16) ? wsum[lane] : 0;
        int winc = wv;
#pragma unroll
        for (int off = 1; off < 16; off <<= 1) {
            int t = __shfl_up_sync(0xFFFFFFFFu, winc, off);
            if (lane >= off) winc += t;
        }
        if (lane < 16) wsum[lane] = winc - wv;     // exclusive warp base
        if (lane == 15) g_bsum[blockIdx.x] = winc; // block total
    }
    __syncthreads();

    if (i < N) g_offs[i] = wsum[w] + inc - v;
}

// Adds cross-block prefix (parallel Hillis-Steele over the 98 partials).
__global__ void k_scan3(int N, int E) {
    __shared__ int sb[128];
    int tid = threadIdx.x;
    if (tid < 128) sb[tid] = (tid < SCAN_NB) ? g_bsum[tid] : 0;
    __syncthreads();
#pragma unroll
    for (int off = 1; off < 128; off <<= 1) {
        int t = (tid < 128 && tid >= off) ? sb[tid - off] : 0;
        __syncthreads();
        if (tid < 128) sb[tid] += t;
        __syncthreads();
    }
    int i = blockIdx.x * blockDim.x + tid;
    if (i < N) {
        int blk = i / SCAN_BLK;
        int base = (blk == 0) ? 0 : sb[blk - 1];   // exclusive prefix
        int o = g_offs[i] + base;
        g_offs[i] = o;
        g_cursor[i] = o;
    }
    if (i == 0) g_offs[N] = E;
}

__global__ void k_fill(const int* __restrict__ src, const int* __restrict__ dst, int E) {
    int e = blockIdx.x * blockDim.x + threadIdx.x;
    if (e < E) {
        int d = dst[e];
        int s = src[e];
        int pos = atomicAdd(&g_cursor[d], 1);
        g_edge[pos] = make_int2(s, __float_as_int(g_dinv[s] * g_dinv[d]));
    }
}

// GEMM1: X[N,128] @ W[128,64] -> g_XW (fp16). 128 rows/block, 256 threads, 8 rows/thread.
__global__ __launch_bounds__(256) void k_gemm1(const float* __restrict__ X,
                                               const float* __restrict__ W, int N) {
    __shared__ float Ws[INDIM * HIDC];
    for (int i = threadIdx.x; i < INDIM * HIDC / 4; i += 256)
        reinterpret_cast<float4*>(Ws)[i] = reinterpret_cast<const float4*>(W)[i];
    __syncthreads();

    const int q  = threadIdx.x & 15;
    const int rg = threadIdx.x >> 4;       // 0..15
    const int row0 = blockIdx.x * 128;

    float4 acc[8];
    int rows[8]; bool valid[8];
#pragma unroll
    for (int rr = 0; rr < 8; rr++) {
        rows[rr] = row0 + rg + 16 * rr;
        valid[rr] = rows[rr] < N;
        acc[rr] = make_float4(0.f, 0.f, 0.f, 0.f);
    }

    for (int k4 = 0; k4 < INDIM / 4; k4++) {
        float4 a[8];
#pragma unroll
        for (int rr = 0; rr < 8; rr++)
            a[rr] = valid[rr]
                ? reinterpret_cast<const float4*>(&X[(long long)rows[rr] * INDIM + k4 * 4])[0]
                : make_float4(0.f, 0.f, 0.f, 0.f);
#pragma unroll
        for (int kk = 0; kk < 4; kk++) {
            float4 w = reinterpret_cast<const float4*>(&Ws[(k4 * 4 + kk) * HIDC + q * 4])[0];
#pragma unroll
            for (int rr = 0; rr < 8; rr++) {
                float av = (&a[rr].x)[kk];
                acc[rr] = fma4(w, av, acc[rr]);
            }
        }
    }
#pragma unroll
    for (int rr = 0; rr < 8; rr++) {
        if (valid[rr]) {
            uint2 p;
            reinterpret_cast<__half2*>(&p)[0] = __floats2half2_rn(acc[rr].x, acc[rr].y);
            reinterpret_cast<__half2*>(&p)[1] = __floats2half2_rn(acc[rr].z, acc[rr].w);
            *reinterpret_cast<uint2*>(&g_XW[(long long)rows[rr] * HIDC + q * 4]) = p;
        }
    }
}

// Layer-1 CSR gather + self-loop + bias + ELU -> g_h1. 8 lanes/node, 8 floats/lane.
__global__ void k_gather1(const float* __restrict__ b1, int N) {
    long long idx = (long long)blockIdx.x * blockDim.x + threadIdx.x;
    if (idx >= (long long)N * 8) return;
    int node = (int)(idx >> 3);
    int c    = (int)(idx & 7);
    float di = g_dinv[node];
    float self = di * di;

    float acc[8];
    {
        uint4 v = *reinterpret_cast<const uint4*>(&g_XW[(long long)node * HIDC + c * 8]);
        const __half2* h = reinterpret_cast<const __half2*>(&v);
#pragma unroll
        for (int j = 0; j < 4; j++) {
            float2 f = __half22float2(h[j]);
            acc[2 * j]     = f.x * self;
            acc[2 * j + 1] = f.y * self;
        }
    }
    csr_gather_h(g_XW, node, c, acc);

#pragma unroll
    for (int j = 0; j < 8; j++) {
        acc[j] += b1[c * 8 + j];
        acc[j] = elu1(acc[j]);
    }
    *reinterpret_cast<uint4*>(&g_h1[(long long)node * HIDC + c * 8]) = pack8h(acc);
}

// Fused layer-2: CSR gather h1 into smem tile (64 nodes), then
// z = tile @ {Wmu,Wsig} + bias, ELU, mean-pool accumulate. 256 threads/block.
__global__ __launch_bounds__(256) void k_gather2gemm2pool(
        const float* __restrict__ Wmu, const float* __restrict__ bmu,
        const float* __restrict__ Wsig, const float* __restrict__ bsig,
        const int* __restrict__ batch, int N) {
    __shared__ float Wms[HIDC * HIDC];
    __shared__ float Wss[HIDC * HIDC];
    __shared__ float tile[64 * HIDC];   // 16 KB
    __shared__ float spool[128];        // 64 mu + 64 sig

    for (int i = threadIdx.x; i < HIDC * HIDC / 4; i += 256) {
        reinterpret_cast<float4*>(Wms)[i] = reinterpret_cast<const float4*>(Wmu)[i];
        reinterpret_cast<float4*>(Wss)[i] = reinterpret_cast<const float4*>(Wsig)[i];
    }
    if (threadIdx.x < 128) spool[threadIdx.x] = 0.f;

    const int row0 = blockIdx.x * 64;

    // ---- Phase A: gather 64 nodes into smem tile (8 lanes/node, 2 nodes/thread) ----
    {
        int c  = threadIdx.x & 7;      // 8-half slice
        int ng = threadIdx.x >> 3;     // 0..31
#pragma unroll
        for (int pp = 0; pp < 2; pp++) {
            int ln = ng + 32 * pp;     // local node 0..63
            int node = row0 + ln;
            float acc[8];
            if (node < N) {
                float di = g_dinv[node];
                float self = di * di;
                uint4 v = *reinterpret_cast<const uint4*>(&g_h1[(long long)node * HIDC + c * 8]);
                const __half2* h = reinterpret_cast<const __half2*>(&v);
#pragma unroll
                for (int j = 0; j < 4; j++) {
                    float2 f = __half22float2(h[j]);
                    acc[2 * j]     = f.x * self;
                    acc[2 * j + 1] = f.y * self;
                }
                csr_gather_h(g_h1, node, c, acc);
            } else {
#pragma unroll
                for (int j = 0; j < 8; j++) acc[j] = 0.f;
            }
            reinterpret_cast<float4*>(&tile[ln * HIDC + c * 8])[0] =
                make_float4(acc[0], acc[1], acc[2], acc[3]);
            reinterpret_cast<float4*>(&tile[ln * HIDC + c * 8 + 4])[0] =
                make_float4(acc[4], acc[5], acc[6], acc[7]);
        }
    }
    __syncthreads();

    // ---- Phase B: dual GEMM from smem + bias + ELU + pool ----
    const int q  = threadIdx.x & 15;
    const int rg = threadIdx.x >> 4;   // 0..15

    float4 am[4], as4[4];
    int rows[4]; bool valid[4];
#pragma unroll
    for (int rr = 0; rr < 4; rr++) {
        rows[rr] = row0 + rg + 16 * rr;
        valid[rr] = rows[rr] < N;
        am[rr]  = make_float4(0.f, 0.f, 0.f, 0.f);
        as4[rr] = make_float4(0.f, 0.f, 0.f, 0.f);
    }

    for (int k4 = 0; k4 < HIDC / 4; k4++) {
        float4 a[4];
#pragma unroll
        for (int rr = 0; rr < 4; rr++)
            a[rr] = reinterpret_cast<const float4*>(&tile[(rg + 16 * rr) * HIDC + k4 * 4])[0];
#pragma unroll
        for (int kk = 0; kk < 4; kk++) {
            float4 wm = reinterpret_cast<const float4*>(&Wms[(k4 * 4 + kk) * HIDC + q * 4])[0];
            float4 ws = reinterpret_cast<const float4*>(&Wss[(k4 * 4 + kk) * HIDC + q * 4])[0];
#pragma unroll
            for (int rr = 0; rr < 4; rr++) {
                float av = (&a[rr].x)[kk];
                am[rr]  = fma4(wm, av, am[rr]);
                as4[rr] = fma4(ws, av, as4[rr]);
            }
        }
    }

    float4 bbm = reinterpret_cast<const float4*>(&bmu[q * 4])[0];
    float4 bbs = reinterpret_cast<const float4*>(&bsig[q * 4])[0];
#pragma unroll
    for (int rr = 0; rr < 4; rr++) {
        am[rr]  = elu4(add4(am[rr], bbm));
        as4[rr] = elu4(add4(as4[rr], bbs));
    }

    int lastRow = min(row0 + 63, N - 1);
    int g0 = batch[row0];
    int g1 = batch[lastRow];

    if (g0 == g1) {
        float4 sm = make_float4(0.f, 0.f, 0.f, 0.f);
        float4 ss = make_float4(0.f, 0.f, 0.f, 0.f);
#pragma unroll
        for (int rr = 0; rr < 4; rr++) {
            if (valid[rr]) { sm = add4(sm, am[rr]); ss = add4(ss, as4[rr]); }
        }
        atomicAdd(&spool[q * 4 + 0], sm.x);
        atomicAdd(&spool[q * 4 + 1], sm.y);
        atomicAdd(&spool[q * 4 + 2], sm.z);
        atomicAdd(&spool[q * 4 + 3], sm.w);
        atomicAdd(&spool[64 + q * 4 + 0], ss.x);
        atomicAdd(&spool[64 + q * 4 + 1], ss.y);
        atomicAdd(&spool[64 + q * 4 + 2], ss.z);
        atomicAdd(&spool[64 + q * 4 + 3], ss.w);
        __syncthreads();
        if (threadIdx.x < 32) {
            int half = threadIdx.x >> 4;
            int cc   = threadIdx.x & 15;
            float4 v = reinterpret_cast<const float4*>(&spool[half * 64 + cc * 4])[0];
            red_add_f32x4(&g_sums[(long long)(half * 64 + g0) * HIDC + cc * 4], v);
        }
        if (threadIdx.x == 0) {
            int cnt = min(N - row0, 64);
            red_add_f32(&g_cntf[g0], (float)cnt);
        }
    } else {
#pragma unroll
        for (int rr = 0; rr < 4; rr++) {
            if (!valid[rr]) continue;
            int g = batch[rows[rr]];
            red_add_f32x4(&g_sums[(long long)(0 * 64 + g) * HIDC + q * 4], am[rr]);
            red_add_f32x4(&g_sums[(long long)(1 * 64 + g) * HIDC + q * 4], as4[rr]);
            if (q == 0) red_add_f32(&g_cntf[g], 1.0f);
        }
    }
}

// Final: divide by counts, write [z_mu ; z_sigma] to d_out.
__global__ void k_final(float* __restrict__ out, int G) {
    int tid = blockIdx.x * blockDim.x + threadIdx.x;
    int total = 2 * G * HIDC;
    if (tid >= total) return;
    int t = tid / (G * HIDC);
    int rem = tid - t * G * HIDC;
    int g = rem >> 6;
    int c = rem & 63;
    float cnt = fmaxf(g_cntf[g], 1.0f);
    out[tid] = g_sums[(long long)(t * 64 + g) * HIDC + c] / cnt;
}

// ---------------- launch ----------------
extern "C" void kernel_launch(void* const* d_in, const int* in_sizes, int n_in,
                              void* d_out, int out_size) {
    const float* x     = (const float*)d_in[0];
    const int*   ei    = (const int*)d_in[1];
    const int*   batch = (const int*)d_in[2];

    int N = in_sizes[0] / INDIM;   // 50000
    int E = in_sizes[1] / 2;       // 800000
    int G = out_size / (2 * HIDC); // 64

    int wi = 3;
    if (in_sizes[3] == 1) wi = 4;  // num_graphs may be materialized
    const float* W1   = (const float*)d_in[wi + 0];
    const float* b1   = (const float*)d_in[wi + 1];
    const float* Wmu  = (const float*)d_in[wi + 2];
    const float* bmu  = (const float*)d_in[wi + 3];
    const float* Wsig = (const float*)d_in[wi + 4];
    const float* bsig = (const float*)d_in[wi + 5];
    float* out = (float*)d_out;

    const int* src = ei;
    const int* dst = ei + E;

    // Fork-join: CSR build chain on the main (capture) stream; gemm1 + sums
    // zeroing + cnt re-zero on a side stream. ALL side-stream work is joined
    // back into stream 0 before capture ends (evJ before gather1, evZ before
    // k_final) so the graph has a single sink.
    cudaStream_t s2;
    cudaStreamCreateWithFlags(&s2, cudaStreamNonBlocking);
    cudaEvent_t evF, evJ, evS, evZ;
    cudaEventCreateWithFlags(&evF, cudaEventDisableTiming);
    cudaEventCreateWithFlags(&evJ, cudaEventDisableTiming);
    cudaEventCreateWithFlags(&evS, cudaEventDisableTiming);
    cudaEventCreateWithFlags(&evZ, cudaEventDisableTiming);

    cudaEventRecord(evF, 0);
    cudaStreamWaitEvent(s2, evF, 0);
    k_zero_sums<<<(2 * 64 * 64 + 255) / 256, 256, 0, s2>>>();   // branch B
    k_gemm1<<<(N + 127) / 128, 256, 0, s2>>>(x, W1, N);
    cudaEventRecord(evJ, s2);

    // branch A: CSR build (g_cnt arrives zeroed: module-load zero-init on the
    // first call; re-zeroed below on every call after scan1 consumes it).
    k_deg<<<(E + 255) / 256, 256>>>(dst, E);
    k_scan1<<<SCAN_NB, SCAN_BLK>>>(N);
    cudaEventRecord(evS, 0);
    k_scan3<<<(N + 255) / 256, 256>>>(N, E);
    k_fill<<<(E + 255) / 256, 256>>>(src, dst, E);

    // side stream: re-zero g_cnt once scan1 has read it (hidden under k_fill).
    cudaStreamWaitEvent(s2, evS, 0);
    k_zero_cnt<<<(NN / 4 + 255) / 256, 256, 0, s2>>>();
    cudaEventRecord(evZ, s2);

    cudaStreamWaitEvent(0, evJ, 0);   // join (gemm1 + zero_sums) before gather1

    {
        long long t = (long long)N * 8;
        k_gather1<<<(unsigned)((t + 255) / 256), 256>>>(b1, N);
    }
    k_gather2gemm2pool<<<(N + 63) / 64, 256>>>(Wmu, bmu, Wsig, bsig, batch, N);

    cudaStreamWaitEvent(0, evZ, 0);   // fold cnt re-zero into the main chain
    k_final<<<(2 * G * HIDC + 255) / 256, 256>>>(out, G);

    cudaEventDestroy(evF);
    cudaEventDestroy(evJ);
    cudaEventDestroy(evS);
    cudaEventDestroy(evZ);
    cudaStreamDestroy(s2);
}